// round 14
// baseline (speedup 1.0000x reference)
#include <cuda_runtime.h>
#include <cuda_bf16.h>

// y[b] = sum over segments s of w[s]*f_s; f_s picks highest-m valid candidate
// (m, l=s-3m) with x[m] in (phi-iv[m], phi+iv[m]], value 0.5*cos(x[m]-phi)+0.5.
// Per row: y = C0 cos x0 + S0 sin x0 + C1 cos x1 + S1 sin x1 + C2 cos x2 + S2 sin x2 + T
// with coefficients a function of the rank triple (r0,r1,r2) of x[m] among
// each m's 32 sorted window bounds.
//   (C0,S0,T_total) = f(r0,r1,r2) -> 33^3 L2 table, 16B = 1 sector, 1 LDG (cg)
//   (C1,S1,C2,S2)   = f(r1,r2)    -> 1089-entry smem table, 1 LDS.128
// Rank: 4 scalar-smem binary-search levels + 1 LDS.64 + 2 compares.
// TPB=512 + __launch_bounds__(512,3): 1536 threads/SM (75% occ) at <=42 regs —
// L1-feed is the binding resource and utilization tracks occupancy.
// Output: [ y (batch floats), weight (48 floats) ].

#define TPB 512
#define RPT 4
#define NR    33
#define NPAIR (NR * NR)       // 1089
#define NTAB  (NR * NR * NR)  // 35937

__device__ float  gSortedB[96];     // [m*32 + pos]
__device__ float4 gTrip[NTAB];      // (C0, S0, T_total, 0)
__device__ float4 gPairQ[NPAIR];    // (C1, S1, C2, S2)

// ---------------- fused setup ----------------------------------------------
__global__ void __launch_bounds__(256)
setup_all(const float* __restrict__ phis,
          const float* __restrict__ interval,
          const float* __restrict__ weight) {
    __shared__ float    sv[96];
    __shared__ int      spos[96];
    __shared__ float    svc[3][3][16];   // [m][{c,s,t}][l]
    __shared__ unsigned sSH[3][NR];

    const int t = threadIdx.x;

    if (t < 96) {
        const int m = t >> 5, i = t & 31, l = i & 15;
        const float p  = phis[m * 16 + l];
        const float iv = interval[m];
        sv[t] = (i < 16) ? (p - iv) : (p + iv);
    }
    if (t < 48) {
        const int m = t >> 4, l = t & 15;
        const float w = 0.5f * weight[3 * m + l];    // segment s = 3m + l
        const float p = phis[m * 16 + l];
        float sp, cp;
        sincosf(p, &sp, &cp);
        svc[m][0][l] = w * cp;
        svc[m][1][l] = w * sp;
        svc[m][2][l] = w;
    }
    __syncthreads();

    // stable rank-sort of each m's 32 bounds
    if (t < 96) {
        const int m = t >> 5, i = t & 31;
        const float v = sv[t];
        int pos = 0;
        for (int j = 0; j < 32; ++j) {
            const float u = sv[(m << 5) + j];
            pos += (u < v || (u == v && j < i)) ? 1 : 0;
        }
        spos[t] = pos;
        if (blockIdx.x == 0) gSortedB[(m << 5) + pos] = v;
    }
    __syncthreads();

    // hitmask per rank r in segment space: cond_l <=> pos(lo)<r && pos(hi)>=r
    if (t < 3 * NR) {
        const int m = t / NR, r = t - m * NR;
        unsigned mask = 0;
        for (int l = 0; l < 16; ++l) {
            const int plo  = spos[(m << 5) + l];
            const int phi_ = spos[(m << 5) + 16 + l];
            if (plo < r && phi_ >= r) mask |= (1u << l);
        }
        sSH[m][r] = mask << (3 * m);
    }
    __syncthreads();

    if (blockIdx.x == 0) {
        // pair table: W1 = H1 & ~H2, W2 = H2 (trig parts; T folded into triple)
        for (int e = t; e < NPAIR; e += blockDim.x) {
            const int r1 = e / NR, r2 = e - r1 * NR;
            const unsigned h2 = sSH[2][r2];
            const unsigned W1 = sSH[1][r1] & ~h2;
            float C1 = 0.f, S1 = 0.f, C2 = 0.f, S2 = 0.f;
            for (int l = 0; l < 16; ++l) {
                if (W1 & (1u << (3 + l))) { C1 += svc[1][0][l]; S1 += svc[1][1][l]; }
                if (h2 & (1u << (6 + l))) { C2 += svc[2][0][l]; S2 += svc[2][1][l]; }
            }
            gPairQ[e] = make_float4(C1, S1, C2, S2);
        }
    }

    // triple table: W0 = H0 & ~H1 & ~H2; T_total = T0 + T1 + T2
    for (int e = blockIdx.x * blockDim.x + t; e < NTAB; e += gridDim.x * blockDim.x) {
        const int r0  = e / NPAIR;
        const int rem = e - r0 * NPAIR;
        const int r1  = rem / NR;
        const int r2  = rem - r1 * NR;
        const unsigned h1 = sSH[1][r1], h2 = sSH[2][r2];
        const unsigned W0 = sSH[0][r0] & ~h1 & ~h2;
        const unsigned W1 = h1 & ~h2;
        float C = 0.f, S = 0.f, T = 0.f;
        for (int l = 0; l < 16; ++l) {
            if (W0 & (1u << l))       { C += svc[0][0][l]; S += svc[0][1][l]; T += svc[0][2][l]; }
            if (W1 & (1u << (3 + l))) { T += svc[1][2][l]; }
            if (h2 & (1u << (6 + l))) { T += svc[2][2][l]; }
        }
        gTrip[e] = make_float4(C, S, T, 0.0f);
    }
}

// ---------------- main ------------------------------------------------------
// rank = #{bounds < x}: 4 scalar-smem levels (conflict-free banks) + LDS.64.
__device__ __forceinline__ int rank32s(const float* __restrict__ b, float xv) {
    int r = 0;
    if (b[15]    < xv) r = 16;
    if (b[r + 7] < xv) r += 8;
    if (b[r + 3] < xv) r += 4;
    if (b[r + 1] < xv) r += 2;
    const float2 q = *reinterpret_cast<const float2*>(b + r);  // 8B-aligned
    r += (q.x < xv) + (q.y < xv);
    return r;
}

// L2-only cached 16B load (gather has no L1 reuse; don't pollute L1)
__device__ __forceinline__ float4 ldcg4(const float4* p) {
    float4 v;
    asm volatile("ld.global.cg.v4.f32 {%0,%1,%2,%3}, [%4];"
                 : "=f"(v.x), "=f"(v.y), "=f"(v.z), "=f"(v.w) : "l"(p));
    return v;
}

__global__ void __launch_bounds__(TPB, 3)
glm_main(const float* __restrict__ x,
         const float* __restrict__ weight,
         float* __restrict__ out, int batch) {
    __shared__ float  sb[96];
    __shared__ float4 sPQ[NPAIR];

    const int t = threadIdx.x;
    if (t < 96) sb[t] = gSortedB[t];
    for (int i = t; i < NPAIR; i += TPB) sPQ[i] = gPairQ[i];
    if (blockIdx.x == 0 && t < 48) out[batch + t] = weight[t];  // weight tail
    __syncthreads();

    const int tid = blockIdx.x * TPB + t;
    const long long row0 = (long long)tid * RPT;
    if (row0 >= batch) return;

    const float4* xv = reinterpret_cast<const float4*>(x + row0 * 3);
    const float4 va = xv[0], vb = xv[1], vc = xv[2];
    const float X[RPT][3] = {
        {va.x, va.y, va.z}, {va.w, vb.x, vb.y},
        {vb.z, vb.w, vc.x}, {vc.y, vc.z, vc.w}
    };

    float Y[RPT];
#pragma unroll
    for (int r = 0; r < RPT; ++r) {
        const float x0 = X[r][0], x1 = X[r][1], x2 = X[r][2];
        const int ra = rank32s(sb,      x0);
        const int rb = rank32s(sb + 32, x1);
        const int rc = rank32s(sb + 64, x2);
        const int e12 = rb * NR + rc;

        const float4 tv = ldcg4(&gTrip[ra * NPAIR + e12]);  // 1 sector, L2-only
        const float4 pq = sPQ[e12];

        float s0, c0, s1, c1, s2, c2;
        __sincosf(x0, &s0, &c0);
        __sincosf(x1, &s1, &c1);
        __sincosf(x2, &s2, &c2);

        float y = tv.z;                       // T_total
        y = fmaf(c0, tv.x, y); y = fmaf(s0, tv.y, y);
        y = fmaf(c1, pq.x, y); y = fmaf(s1, pq.y, y);
        y = fmaf(c2, pq.z, y); y = fmaf(s2, pq.w, y);
        Y[r] = y;
    }

    reinterpret_cast<float4*>(out)[tid] = make_float4(Y[0], Y[1], Y[2], Y[3]);
}

extern "C" void kernel_launch(void* const* d_in, const int* in_sizes, int n_in,
                              void* d_out, int out_size) {
    const float* x        = (const float*)d_in[0];
    const float* phis     = (const float*)d_in[1];
    const float* interval = (const float*)d_in[2];
    const float* weight   = (const float*)d_in[3];
    float* out = (float*)d_out;

    const int batch = in_sizes[0] / 3;
    const int n_threads = (batch + RPT - 1) / RPT;
    const int n_blocks  = (n_threads + TPB - 1) / TPB;

    setup_all<<<(NTAB + 255) / 256, 256>>>(phis, interval, weight);
    glm_main<<<n_blocks, TPB>>>(x, weight, out, batch);
}

// round 15
// speedup vs baseline: 1.2545x; 1.2545x over previous
#include <cuda_runtime.h>
#include <cuda_bf16.h>

// y[b] = sum over segments s of w[s]*f_s; f_s picks highest-m valid candidate
// (m, l=s-3m) with x[m] in (phi-iv[m], phi+iv[m]], value 0.5*cos(x[m]-phi)+0.5.
// Per row: y = C0 cos x0 + S0 sin x0 + C1 cos x1 + S1 sin x1 + C2 cos x2 + S2 sin x2 + T
// with coefficients a function of the rank triple (r0,r1,r2) of x[m] among
// each m's 32 sorted window bounds.
//   (C0,S0,T_total) = f(r0,r1,r2) -> 33^3 L2/L1 table, 16B = 1 sector, 1 LDG.128
//   (C1,S1,C2,S2)   = f(r1,r2)    -> 1089-entry smem table, 1 LDS.128
// Rank: 4 scalar-smem binary-search levels + 1 LDS.64 + 2 compares.
// glm_main is PERSISTENT: 888 blocks (148 SM x 6 resident @ 40 regs) grid-stride
// over tiles, so the 17.4KB pair-table smem staging happens once per resident
// block instead of once per tile (deletes ~55% of staging L2 traffic).
// Output: [ y (batch floats), weight (48 floats) ].

#define TPB 256
#define RPT 4
#define NR    33
#define NPAIR (NR * NR)       // 1089
#define NTAB  (NR * NR * NR)  // 35937
#define NBLK  888             // 148 SMs * 6 blocks/SM

__device__ float  gSortedB[96];     // [m*32 + pos]
__device__ float4 gTrip[NTAB];      // (C0, S0, T_total, 0)
__device__ float4 gPairQ[NPAIR];    // (C1, S1, C2, S2)

// ---------------- fused setup ----------------------------------------------
__global__ void __launch_bounds__(256)
setup_all(const float* __restrict__ phis,
          const float* __restrict__ interval,
          const float* __restrict__ weight) {
    __shared__ float    sv[96];
    __shared__ int      spos[96];
    __shared__ float    svc[3][3][16];   // [m][{c,s,t}][l]
    __shared__ unsigned sSH[3][NR];

    const int t = threadIdx.x;

    if (t < 96) {
        const int m = t >> 5, i = t & 31, l = i & 15;
        const float p  = phis[m * 16 + l];
        const float iv = interval[m];
        sv[t] = (i < 16) ? (p - iv) : (p + iv);
    }
    if (t < 48) {
        const int m = t >> 4, l = t & 15;
        const float w = 0.5f * weight[3 * m + l];    // segment s = 3m + l
        const float p = phis[m * 16 + l];
        float sp, cp;
        sincosf(p, &sp, &cp);
        svc[m][0][l] = w * cp;
        svc[m][1][l] = w * sp;
        svc[m][2][l] = w;
    }
    __syncthreads();

    // stable rank-sort of each m's 32 bounds
    if (t < 96) {
        const int m = t >> 5, i = t & 31;
        const float v = sv[t];
        int pos = 0;
        for (int j = 0; j < 32; ++j) {
            const float u = sv[(m << 5) + j];
            pos += (u < v || (u == v && j < i)) ? 1 : 0;
        }
        spos[t] = pos;
        if (blockIdx.x == 0) gSortedB[(m << 5) + pos] = v;
    }
    __syncthreads();

    // hitmask per rank r in segment space: cond_l <=> pos(lo)<r && pos(hi)>=r
    if (t < 3 * NR) {
        const int m = t / NR, r = t - m * NR;
        unsigned mask = 0;
        for (int l = 0; l < 16; ++l) {
            const int plo  = spos[(m << 5) + l];
            const int phi_ = spos[(m << 5) + 16 + l];
            if (plo < r && phi_ >= r) mask |= (1u << l);
        }
        sSH[m][r] = mask << (3 * m);
    }
    __syncthreads();

    if (blockIdx.x == 0) {
        // pair table: W1 = H1 & ~H2, W2 = H2 (trig parts; T folded into triple)
        for (int e = t; e < NPAIR; e += blockDim.x) {
            const int r1 = e / NR, r2 = e - r1 * NR;
            const unsigned h2 = sSH[2][r2];
            const unsigned W1 = sSH[1][r1] & ~h2;
            float C1 = 0.f, S1 = 0.f, C2 = 0.f, S2 = 0.f;
            for (int l = 0; l < 16; ++l) {
                if (W1 & (1u << (3 + l))) { C1 += svc[1][0][l]; S1 += svc[1][1][l]; }
                if (h2 & (1u << (6 + l))) { C2 += svc[2][0][l]; S2 += svc[2][1][l]; }
            }
            gPairQ[e] = make_float4(C1, S1, C2, S2);
        }
    }

    // triple table: W0 = H0 & ~H1 & ~H2; T_total = T0 + T1 + T2
    for (int e = blockIdx.x * blockDim.x + t; e < NTAB; e += gridDim.x * blockDim.x) {
        const int r0  = e / NPAIR;
        const int rem = e - r0 * NPAIR;
        const int r1  = rem / NR;
        const int r2  = rem - r1 * NR;
        const unsigned h1 = sSH[1][r1], h2 = sSH[2][r2];
        const unsigned W0 = sSH[0][r0] & ~h1 & ~h2;
        const unsigned W1 = h1 & ~h2;
        float C = 0.f, S = 0.f, T = 0.f;
        for (int l = 0; l < 16; ++l) {
            if (W0 & (1u << l))       { C += svc[0][0][l]; S += svc[0][1][l]; T += svc[0][2][l]; }
            if (W1 & (1u << (3 + l))) { T += svc[1][2][l]; }
            if (h2 & (1u << (6 + l))) { T += svc[2][2][l]; }
        }
        gTrip[e] = make_float4(C, S, T, 0.0f);
    }
}

// ---------------- main ------------------------------------------------------
// rank = #{bounds < x}: 4 scalar-smem levels (conflict-free banks) + LDS.64.
__device__ __forceinline__ int rank32s(const float* __restrict__ b, float xv) {
    int r = 0;
    if (b[15]    < xv) r = 16;
    if (b[r + 7] < xv) r += 8;
    if (b[r + 3] < xv) r += 4;
    if (b[r + 1] < xv) r += 2;
    const float2 q = *reinterpret_cast<const float2*>(b + r);  // 8B-aligned
    r += (q.x < xv) + (q.y < xv);
    return r;
}

__global__ void __launch_bounds__(TPB, 6)
glm_main(const float* __restrict__ x,
         const float* __restrict__ weight,
         float* __restrict__ out, int batch, int ntile) {
    __shared__ float  sb[96];
    __shared__ float4 sPQ[NPAIR];

    const int t = threadIdx.x;
    if (t < 96) sb[t] = gSortedB[t];
    for (int i = t; i < NPAIR; i += TPB) sPQ[i] = gPairQ[i];
    if (blockIdx.x == 0 && t < 48) out[batch + t] = weight[t];  // weight tail
    __syncthreads();

    // persistent grid-stride over tiles: staging above happens once per block
    for (int tile = blockIdx.x; tile < ntile; tile += gridDim.x) {
        const int tid = tile * TPB + t;
        const long long row0 = (long long)tid * RPT;
        if (row0 >= batch) continue;

        const float4* xv = reinterpret_cast<const float4*>(x + row0 * 3);
        const float4 va = xv[0], vb = xv[1], vc = xv[2];
        const float X[RPT][3] = {
            {va.x, va.y, va.z}, {va.w, vb.x, vb.y},
            {vb.z, vb.w, vc.x}, {vc.y, vc.z, vc.w}
        };

        float Y[RPT];
#pragma unroll
        for (int r = 0; r < RPT; ++r) {
            const float x0 = X[r][0], x1 = X[r][1], x2 = X[r][2];
            const int ra = rank32s(sb,      x0);
            const int rb = rank32s(sb + 32, x1);
            const int rc = rank32s(sb + 64, x2);
            const int e12 = rb * NR + rc;

            const float4 tv = __ldg(&gTrip[ra * NPAIR + e12]);  // 1 sector
            const float4 pq = sPQ[e12];

            float s0, c0, s1, c1, s2, c2;
            __sincosf(x0, &s0, &c0);
            __sincosf(x1, &s1, &c1);
            __sincosf(x2, &s2, &c2);

            float y = tv.z;                       // T_total
            y = fmaf(c0, tv.x, y); y = fmaf(s0, tv.y, y);
            y = fmaf(c1, pq.x, y); y = fmaf(s1, pq.y, y);
            y = fmaf(c2, pq.z, y); y = fmaf(s2, pq.w, y);
            Y[r] = y;
        }

        reinterpret_cast<float4*>(out)[tid] = make_float4(Y[0], Y[1], Y[2], Y[3]);
    }
}

extern "C" void kernel_launch(void* const* d_in, const int* in_sizes, int n_in,
                              void* d_out, int out_size) {
    const float* x        = (const float*)d_in[0];
    const float* phis     = (const float*)d_in[1];
    const float* interval = (const float*)d_in[2];
    const float* weight   = (const float*)d_in[3];
    float* out = (float*)d_out;

    const int batch = in_sizes[0] / 3;
    const int n_threads = (batch + RPT - 1) / RPT;
    const int ntile     = (n_threads + TPB - 1) / TPB;
    const int n_blocks  = (ntile < NBLK) ? ntile : NBLK;

    setup_all<<<(NTAB + 255) / 256, 256>>>(phis, interval, weight);
    glm_main<<<n_blocks, TPB>>>(x, weight, out, batch, ntile);
}